// round 14
// baseline (speedup 1.0000x reference)
#include <cuda_runtime.h>
#include <cuda_bf16.h>
#include <math.h>

#define NODES 100000
#define NEDGES 3200000
#define INC 512
#define HIDC 256
#define OUTC 16
#define KITER 10
#define SCAN_B 1024
#define NSCANB ((NODES + SCAN_B - 1) / SCAN_B)   // 98

// ---------------- scratch (static device globals; no allocation) ----------------
__device__ __align__(16) float g_h0[NODES * OUTC];   // unscaled MLP output
__device__ __align__(16) float g_hA[NODES * OUTC];   // scaled h' ping
__device__ __align__(16) float g_hB[NODES * OUTC];   // scaled h' pong
__device__ float g_dinv[NODES];
__device__ int   g_deg[NODES];
__device__ int   g_cnt[NODES];
__device__ int   g_rexcl[NODES];
__device__ int   g_bsum[NSCANB];
__device__ int   g_boff[NSCANB];
__device__ int   g_rowptr[NODES + 1];
__device__ int   g_src[NEDGES];
__device__ int   g_dst[NEDGES];
__device__ int   g_csrc[NEDGES];       // CSR: src ids grouped by dst
__device__ int   g_is64;

__device__ __forceinline__ void red_add_f4(float* addr, float4 v) {
    asm volatile("red.global.add.v4.f32 [%0], {%1, %2, %3, %4};"
                 :: "l"(addr), "f"(v.x), "f"(v.y), "f"(v.z), "f"(v.w)
                 : "memory");
}

__device__ __forceinline__ unsigned bf2_of(float a, float b) {
    __nv_bfloat162 h = __floats2bfloat162_rn(a, b);   // low = a, high = b
    return *reinterpret_cast<unsigned*>(&h);
}

// scaled buffers (1 = hA, 2 = hB)
__device__ __forceinline__ const float4* sel_in(int s) {
    return (const float4*)(s == 1 ? g_hA : g_hB);
}
__device__ __forceinline__ float4* sel_out(int s) {
    return (float4*)(s == 1 ? g_hA : g_hB);
}

// ---------------- dtype detection for edge_index (int32 vs int64) ----------------
__global__ void detect_kernel(const int* __restrict__ ei32) {
    if (threadIdx.x == 0 && blockIdx.x == 0) {
        int s = 0;
#pragma unroll
        for (int i = 0; i < 64; i++) s |= ei32[2 * i + 1];
        g_is64 = (s == 0) ? 1 : 0;
    }
}

// ---------------- init ----------------
__global__ void zero_kernel() {
    int i = blockIdx.x * blockDim.x + threadIdx.x;
    if (i < NODES * OUTC) g_h0[i] = 0.f;
    if (i < NODES) { g_deg[i] = 0; g_cnt[i] = 0; }
}

// ---------------- edge prep ----------------
__global__ void edge_kernel(const void* __restrict__ ei) {
    int e = blockIdx.x * blockDim.x + threadIdx.x;
    if (e >= NEDGES) return;
    int s, d;
    if (g_is64) {
        const long long* p = (const long long*)ei;
        s = (int)p[e];
        d = (int)p[NEDGES + e];
    } else {
        const int* p = (const int*)ei;
        s = p[e];
        d = p[NEDGES + e];
    }
    g_src[e] = s;
    g_dst[e] = d;
    atomicAdd(&g_deg[d], 1);
}

// ---------------- exclusive scan of deg -> rowptr ----------------
__global__ __launch_bounds__(SCAN_B) void scanA_kernel() {
    __shared__ int s[SCAN_B];
    int tid = threadIdx.x;
    int i = blockIdx.x * SCAN_B + tid;
    int v = (i < NODES) ? g_deg[i] : 0;
    s[tid] = v;
    __syncthreads();
#pragma unroll
    for (int off = 1; off < SCAN_B; off <<= 1) {
        int t = (tid >= off) ? s[tid - off] : 0;
        __syncthreads();
        s[tid] += t;
        __syncthreads();
    }
    if (i < NODES) g_rexcl[i] = s[tid] - v;
    if (tid == SCAN_B - 1) g_bsum[blockIdx.x] = s[tid];
}

__global__ __launch_bounds__(128) void scanB_kernel() {
    __shared__ int s[128];
    int tid = threadIdx.x;
    int v = (tid < NSCANB) ? g_bsum[tid] : 0;
    s[tid] = v;
    __syncthreads();
#pragma unroll
    for (int off = 1; off < 128; off <<= 1) {
        int t = (tid >= off) ? s[tid - off] : 0;
        __syncthreads();
        s[tid] += t;
        __syncthreads();
    }
    if (tid < NSCANB) g_boff[tid] = s[tid] - v;   // exclusive
    if (tid == 0) g_rowptr[NODES] = NEDGES;
}

__global__ void scanC_kernel() {
    int i = blockIdx.x * blockDim.x + threadIdx.x;
    if (i >= NODES) return;
    g_rowptr[i] = g_rexcl[i] + g_boff[i >> 10];
}

__global__ void dinv_kernel() {
    int i = blockIdx.x * blockDim.x + threadIdx.x;
    if (i >= NODES) return;
    g_dinv[i] = rsqrtf((float)g_deg[i] + 1.0f);   // +1 = self loop
}

// counting-sort placement: group src by dst
__global__ void place_kernel() {
    int e = blockIdx.x * blockDim.x + threadIdx.x;
    if (e >= NEDGES) return;
    int d = g_dst[e];
    int pos = g_rowptr[d] + atomicAdd(&g_cnt[d], 1);
    g_csrc[pos] = g_src[e];
}

// h'_init = dinv * h0
__global__ void prescale_kernel() {
    int t = blockIdx.x * blockDim.x + threadIdx.x;
    if (t >= NODES * 4) return;
    float di = g_dinv[t >> 2];
    float4 h = ((const float4*)g_h0)[t];
    ((float4*)g_hA)[t] = make_float4(di * h.x, di * h.y, di * h.z, di * h.w);
}

// ---------------- fused MLP: bf16 MMA + double-buffered software pipeline ----------------
#define BM 128
#define BN 64
#define BKK 32              // k elements per tile = 16 pairs
#define NKP 16              // pairs per tile
#define XS_STRIDE 136
#define WS_STRIDE 72
#define BUF_WORDS (NKP * XS_STRIDE + NKP * WS_STRIDE)   // 3328

__device__ __forceinline__ void load_x_tile(const float* __restrict__ x, int bm,
                                            int k0, int tid, float4 v[4]) {
#pragma unroll
    for (int it = 0; it < 4; it++) {
        int l  = tid + it * 256;
        int r  = l & 127;
        int kq = l >> 7;
        int gm = bm + r;
        v[it] = make_float4(0.f, 0.f, 0.f, 0.f);
        if (gm < NODES) v[it] = *(const float4*)(x + (size_t)gm * INC + k0 + kq * 4);
    }
}

__device__ __forceinline__ void load_w_tile(const float* __restrict__ W1, int bn,
                                            int k0, int tid, float4& w0, float4& w1) {
    int kp = tid >> 4;
    int nq = tid & 15;
    const float* wr = W1 + (size_t)(k0 + 2 * kp) * HIDC + bn + nq * 4;
    w0 = *(const float4*)wr;
    w1 = *(const float4*)(wr + HIDC);
}

__device__ __forceinline__ void sts_tile(unsigned* Xp, unsigned* Wp, int tid,
                                         const float4 v[4], float4 w0, float4 w1) {
#pragma unroll
    for (int it = 0; it < 4; it++) {
        int l  = tid + it * 256;
        int r  = l & 127;
        int kq = l >> 7;
        Xp[(kq * 2 + 0) * XS_STRIDE + r] = bf2_of(v[it].x, v[it].y);
        Xp[(kq * 2 + 1) * XS_STRIDE + r] = bf2_of(v[it].z, v[it].w);
    }
    int kp = tid >> 4;
    int nq = tid & 15;
    uint4 t;
    t.x = bf2_of(w0.x, w1.x);
    t.y = bf2_of(w0.y, w1.y);
    t.z = bf2_of(w0.z, w1.z);
    t.w = bf2_of(w0.w, w1.w);
    *(uint4*)(Wp + kp * WS_STRIDE + nq * 4) = t;
}

__global__ __launch_bounds__(256) void mlp_tc_kernel(
    const float* __restrict__ x, const float* __restrict__ W1,
    const float* __restrict__ b1, const float* __restrict__ W2,
    const float* __restrict__ b2)
{
    __shared__ __align__(16) float sm[9344];   // 2*BUF_WORDS=6656 loop; 9344 epilogue
    unsigned* base = (unsigned*)sm;

    const int tid  = threadIdx.x;
    const int lane = tid & 31;
    const int wid  = tid >> 5;
    const int warp_m = wid >> 1;
    const int warp_n = wid & 1;
    const int bm = blockIdx.y * BM;      // m-block on slow axis
    const int bn = blockIdx.x * BN;      // n-block on fast axis (L2 reuse of X)
    const int gID = lane >> 2;
    const int tig = lane & 3;

    float acc[2][4][4];
#pragma unroll
    for (int mt = 0; mt < 2; mt++)
#pragma unroll
        for (int nt = 0; nt < 4; nt++)
#pragma unroll
            for (int v = 0; v < 4; v++) acc[mt][nt][v] = 0.f;

    // prologue: tile 0 -> buffer 0
    {
        float4 xs[4], w0, w1;
        load_x_tile(x, bm, 0, tid, xs);
        load_w_tile(W1, bn, 0, tid, w0, w1);
        sts_tile(base, base + NKP * XS_STRIDE, tid, xs, w0, w1);
    }
    __syncthreads();

    int cur = 0;
    for (int k0 = 0; k0 < INC; k0 += BKK) {
        const bool has_next = (k0 + BKK < INC);
        float4 nxs[4], nw0, nw1;
        if (has_next) {                          // issue next-tile loads early
            load_x_tile(x, bm, k0 + BKK, tid, nxs);
            load_w_tile(W1, bn, k0 + BKK, tid, nw0, nw1);
        }

        unsigned* Xp = base + cur * BUF_WORDS;
        unsigned* Wp = Xp + NKP * XS_STRIDE;

#pragma unroll
        for (int ks = 0; ks < 2; ks++) {          // 2 x k16 per tile
            const int kb = ks * 8;                // pair offset
            unsigned a[2][4], b[4][2];
#pragma unroll
            for (int mt = 0; mt < 2; mt++) {
                int m = warp_m * 32 + mt * 16 + gID;
                a[mt][0] = Xp[(kb + tig) * XS_STRIDE + m];
                a[mt][1] = Xp[(kb + tig) * XS_STRIDE + m + 8];
                a[mt][2] = Xp[(kb + tig + 4) * XS_STRIDE + m];
                a[mt][3] = Xp[(kb + tig + 4) * XS_STRIDE + m + 8];
            }
#pragma unroll
            for (int nt = 0; nt < 4; nt++) {
                int n = warp_n * 32 + nt * 8 + gID;
                b[nt][0] = Wp[(kb + tig) * WS_STRIDE + n];
                b[nt][1] = Wp[(kb + tig + 4) * WS_STRIDE + n];
            }
#pragma unroll
            for (int mt = 0; mt < 2; mt++)
#pragma unroll
                for (int nt = 0; nt < 4; nt++) {
                    float* c = acc[mt][nt];
                    asm volatile(
                        "mma.sync.aligned.m16n8k16.row.col.f32.bf16.bf16.f32 "
                        "{%0,%1,%2,%3}, {%4,%5,%6,%7}, {%8,%9}, {%0,%1,%2,%3};"
                        : "+f"(c[0]), "+f"(c[1]), "+f"(c[2]), "+f"(c[3])
                        : "r"(a[mt][0]), "r"(a[mt][1]), "r"(a[mt][2]), "r"(a[mt][3]),
                          "r"(b[nt][0]), "r"(b[nt][1]));
                }
        }

        if (has_next) {                          // convert+store into alt buffer
            unsigned* Xn = base + (cur ^ 1) * BUF_WORDS;
            sts_tile(Xn, Xn + NKP * XS_STRIDE, tid, nxs, nw0, nw1);
            __syncthreads();
            cur ^= 1;
        }
    }
    __syncthreads();                             // epilogue reuses smem

    // epilogue: bias + relu -> smem tile [128][65]
    float* tile = sm;
    float* W2s  = sm + BM * 65;

#pragma unroll
    for (int mt = 0; mt < 2; mt++) {
        int r0 = warp_m * 32 + mt * 16 + gID;
        int r1 = r0 + 8;
#pragma unroll
        for (int nt = 0; nt < 4; nt++) {
            int c0 = warp_n * 32 + nt * 8 + 2 * tig;
            int c1 = c0 + 1;
            float bc0 = b1[bn + c0];
            float bc1 = b1[bn + c1];
            float v00 = acc[mt][nt][0] + bc0;
            float v01 = acc[mt][nt][1] + bc1;
            float v10 = acc[mt][nt][2] + bc0;
            float v11 = acc[mt][nt][3] + bc1;
            tile[r0 * 65 + c0] = v00 > 0.f ? v00 : 0.f;
            tile[r0 * 65 + c1] = v01 > 0.f ? v01 : 0.f;
            tile[r1 * 65 + c0] = v10 > 0.f ? v10 : 0.f;
            tile[r1 * 65 + c1] = v11 > 0.f ? v11 : 0.f;
        }
    }
    {
        int rr = tid >> 2;
        int cc = (tid & 3) * 4;
        *(float4*)(W2s + rr * OUTC + cc) =
            *(const float4*)(W2 + (size_t)(bn + rr) * OUTC + cc);
    }
    __syncthreads();

    int m2 = tid >> 1;
    int ch = (tid & 1) * 8;
    float acc2[8];
#pragma unroll
    for (int c = 0; c < 8; c++) acc2[c] = (blockIdx.x == 0) ? b2[ch + c] : 0.f;
#pragma unroll 8
    for (int k = 0; k < BN; k++) {
        float v = tile[m2 * 65 + k];
        float4 w0 = *(float4*)(W2s + k * OUTC + ch);
        float4 w1 = *(float4*)(W2s + k * OUTC + ch + 4);
        acc2[0] += v * w0.x; acc2[1] += v * w0.y;
        acc2[2] += v * w0.z; acc2[3] += v * w0.w;
        acc2[4] += v * w1.x; acc2[5] += v * w1.y;
        acc2[6] += v * w1.z; acc2[7] += v * w1.w;
    }
    int gm2 = bm + m2;
    if (gm2 < NODES) {
        red_add_f4(g_h0 + (size_t)gm2 * OUTC + ch,
                   make_float4(acc2[0], acc2[1], acc2[2], acc2[3]));
        red_add_f4(g_h0 + (size_t)gm2 * OUTC + ch + 4,
                   make_float4(acc2[4], acc2[5], acc2[6], acc2[7]));
    }
}

// ---------------- propagation: warp-per-node CSR gather, unroll x4 (R9 best) ----------------
__global__ __launch_bounds__(256) void gather_kernel(int sin, int sout, int final_,
                                                     float* __restrict__ out) {
    int w = (blockIdx.x * blockDim.x + threadIdx.x) >> 5;   // node id
    if (w >= NODES) return;
    const int lane = threadIdx.x & 31;
    const int el   = lane >> 2;    // 0..7  edge slot
    const int q    = lane & 3;     // 0..3  channel quad
    const float4* __restrict__ hin = sel_in(sin);
    const int* __restrict__ csrc = g_csrc;
    const int end = g_rowptr[w + 1];

    float4 a0 = make_float4(0.f, 0.f, 0.f, 0.f);
    float4 a1 = make_float4(0.f, 0.f, 0.f, 0.f);
    int e = g_rowptr[w] + el;
    for (; e + 24 < end; e += 32) {
        int s0 = __ldg(&csrc[e]);
        int s1 = __ldg(&csrc[e + 8]);
        int s2 = __ldg(&csrc[e + 16]);
        int s3 = __ldg(&csrc[e + 24]);
        float4 v0 = hin[s0 * 4 + q];
        float4 v1 = hin[s1 * 4 + q];
        float4 v2 = hin[s2 * 4 + q];
        float4 v3 = hin[s3 * 4 + q];
        a0.x += v0.x + v1.x; a0.y += v0.y + v1.y;
        a0.z += v0.z + v1.z; a0.w += v0.w + v1.w;
        a1.x += v2.x + v3.x; a1.y += v2.y + v3.y;
        a1.z += v2.z + v3.z; a1.w += v2.w + v3.w;
    }
    for (; e < end; e += 8) {
        int s = __ldg(&csrc[e]);
        float4 v = hin[s * 4 + q];
        a0.x += v.x; a0.y += v.y; a0.z += v.z; a0.w += v.w;
    }
    float4 acc = make_float4(a0.x + a1.x, a0.y + a1.y, a0.z + a1.z, a0.w + a1.w);
#pragma unroll
    for (int off = 4; off <= 16; off <<= 1) {
        acc.x += __shfl_xor_sync(0xFFFFFFFFu, acc.x, off);
        acc.y += __shfl_xor_sync(0xFFFFFFFFu, acc.y, off);
        acc.z += __shfl_xor_sync(0xFFFFFFFFu, acc.z, off);
        acc.w += __shfl_xor_sync(0xFFFFFFFFu, acc.w, off);
    }

    float di = g_dinv[w];
    float4 hs  = hin[w * 4 + q];                 // h'[i] (scaled self)
    float4 h0v = ((const float4*)g_h0)[w * 4 + q];
    float4 o;
    o.x = 0.9f * di * (acc.x + hs.x) + 0.1f * h0v.x;
    o.y = 0.9f * di * (acc.y + hs.y) + 0.1f * h0v.y;
    o.z = 0.9f * di * (acc.z + hs.z) + 0.1f * h0v.z;
    o.w = 0.9f * di * (acc.w + hs.w) + 0.1f * h0v.w;

    if (!final_) {
        if (el == 0)
            sel_out(sout)[w * 4 + q] =
                make_float4(di * o.x, di * o.y, di * o.z, di * o.w);
    } else {
        float m = fmaxf(fmaxf(o.x, o.y), fmaxf(o.z, o.w));
        m = fmaxf(m, __shfl_xor_sync(0xFFFFFFFFu, m, 1));
        m = fmaxf(m, __shfl_xor_sync(0xFFFFFFFFu, m, 2));
        float ssum = expf(o.x - m) + expf(o.y - m) + expf(o.z - m) + expf(o.w - m);
        ssum += __shfl_xor_sync(0xFFFFFFFFu, ssum, 1);
        ssum += __shfl_xor_sync(0xFFFFFFFFu, ssum, 2);
        float ls = logf(ssum) + m;
        if (el == 0)
            ((float4*)out)[w * 4 + q] =
                make_float4(o.x - ls, o.y - ls, o.z - ls, o.w - ls);
    }
}

// ---------------- launch ----------------
extern "C" void kernel_launch(void* const* d_in, const int* in_sizes, int n_in,
                              void* d_out, int out_size)
{
    const float* x  = (const float*)d_in[0];
    const void* ei  = d_in[1];
    const float* W1 = (const float*)d_in[2];
    const float* b1 = (const float*)d_in[3];
    const float* W2 = (const float*)d_in[4];
    const float* b2 = (const float*)d_in[5];
    float* out      = (float*)d_out;

    detect_kernel<<<1, 32>>>((const int*)ei);                           // 1
    zero_kernel<<<(NODES * OUTC + 255) / 256, 256>>>();                 // 2
    edge_kernel<<<(NEDGES + 255) / 256, 256>>>(ei);                     // 3
    mlp_tc_kernel<<<dim3(HIDC / BN, (NODES + BM - 1) / BM), 256>>>(     // 4 <- profiled
        x, W1, b1, W2, b2);
    scanA_kernel<<<NSCANB, SCAN_B>>>();
    scanB_kernel<<<1, 128>>>();
    scanC_kernel<<<(NODES + 255) / 256, 256>>>();
    dinv_kernel<<<(NODES + 255) / 256, 256>>>();
    place_kernel<<<(NEDGES + 255) / 256, 256>>>();
    prescale_kernel<<<(NODES * 4 + 255) / 256, 256>>>();

    int cur = 1;
    for (int t = 0; t < KITER; t++) {
        int nxt = (cur == 1) ? 2 : 1;
        int fin = (t == KITER - 1) ? 1 : 0;
        gather_kernel<<<(NODES * 32 + 255) / 256, 256>>>(cur, nxt, fin, out);
        cur = nxt;
    }
}

// round 15
// speedup vs baseline: 1.5809x; 1.5809x over previous
#include <cuda_runtime.h>
#include <cuda_bf16.h>
#include <math.h>

#define NODES 100000
#define NODESP (NODES + 128)     // padded rows for OOB-safe cp.async
#define NEDGES 3200000
#define INC 512
#define HIDC 256
#define OUTC 16
#define KITER 10
#define SCAN_B 1024
#define NSCANB ((NODES + SCAN_B - 1) / SCAN_B)   // 98

// ---------------- scratch (static device globals; no allocation) ----------------
__device__ __align__(16) float g_h0[NODES * OUTC];   // unscaled MLP output
__device__ __align__(16) float g_hA[NODES * OUTC];   // scaled h' ping
__device__ __align__(16) float g_hB[NODES * OUTC];   // scaled h' pong
__device__ __align__(16) unsigned g_xp[(size_t)NODESP * 256]; // bf16-pair X [m][kpair]
__device__ __align__(16) unsigned g_w1p[HIDC * 256];          // bf16-pair W1^T [n][kpair]
__device__ float g_dinv[NODES];
__device__ int   g_deg[NODES];
__device__ int   g_cnt[NODES];
__device__ int   g_rexcl[NODES];
__device__ int   g_bsum[NSCANB];
__device__ int   g_boff[NSCANB];
__device__ int   g_rowptr[NODES + 1];
__device__ int   g_src[NEDGES];
__device__ int   g_dst[NEDGES];
__device__ int   g_csrc[NEDGES];       // CSR: src ids grouped by dst
__device__ int   g_is64;

__device__ __forceinline__ void red_add_f4(float* addr, float4 v) {
    asm volatile("red.global.add.v4.f32 [%0], {%1, %2, %3, %4};"
                 :: "l"(addr), "f"(v.x), "f"(v.y), "f"(v.z), "f"(v.w)
                 : "memory");
}

__device__ __forceinline__ unsigned bf2_of(float a, float b) {
    __nv_bfloat162 h = __floats2bfloat162_rn(a, b);   // low = a, high = b
    return *reinterpret_cast<unsigned*>(&h);
}

__device__ __forceinline__ void cp_async16(void* smem_ptr, const void* gptr) {
    unsigned saddr = (unsigned)__cvta_generic_to_shared(smem_ptr);
    asm volatile("cp.async.ca.shared.global [%0], [%1], 16;"
                 :: "r"(saddr), "l"(gptr) : "memory");
}
#define CP_COMMIT() asm volatile("cp.async.commit_group;" ::: "memory")
#define CP_WAIT0()  asm volatile("cp.async.wait_group 0;" ::: "memory")

// scaled buffers (1 = hA, 2 = hB)
__device__ __forceinline__ const float4* sel_in(int s) {
    return (const float4*)(s == 1 ? g_hA : g_hB);
}
__device__ __forceinline__ float4* sel_out(int s) {
    return (float4*)(s == 1 ? g_hA : g_hB);
}

// ---------------- dtype detection for edge_index (int32 vs int64) ----------------
__global__ void detect_kernel(const int* __restrict__ ei32) {
    if (threadIdx.x == 0 && blockIdx.x == 0) {
        int s = 0;
#pragma unroll
        for (int i = 0; i < 64; i++) s |= ei32[2 * i + 1];
        g_is64 = (s == 0) ? 1 : 0;
    }
}

// ---------------- init ----------------
__global__ void zero_kernel() {
    int i = blockIdx.x * blockDim.x + threadIdx.x;
    if (i < NODES * OUTC) g_h0[i] = 0.f;
    if (i < NODES) { g_deg[i] = 0; g_cnt[i] = 0; }
}

// ---------------- one-time bf16 conversion: X -> g_xp, W1^T -> g_w1p ----------------
__global__ void conv_kernel(const float* __restrict__ x, const float* __restrict__ W1) {
    int i = blockIdx.x * blockDim.x + threadIdx.x;
    const int NXT = NODESP * 128;                 // X work items (2 pairs each)
    if (i < NXT) {
        int row = i >> 7;
        int q   = i & 127;
        uint2 o = make_uint2(0u, 0u);
        if (row < NODES) {
            float4 v = *(const float4*)(x + (size_t)row * INC + q * 4);
            o.x = bf2_of(v.x, v.y);
            o.y = bf2_of(v.z, v.w);
        }
        *(uint2*)(g_xp + (size_t)row * 256 + q * 2) = o;
    } else {
        int j = i - NXT;
        if (j < HIDC * 256) {                     // W1 pairs
            int p = j >> 8;                       // kpair 0..255
            int n = j & 255;                      // coalesced reads along n
            g_w1p[n * 256 + p] =
                bf2_of(W1[(size_t)(2 * p) * HIDC + n],
                       W1[(size_t)(2 * p + 1) * HIDC + n]);
        }
    }
}

// ---------------- edge prep ----------------
__global__ void edge_kernel(const void* __restrict__ ei) {
    int e = blockIdx.x * blockDim.x + threadIdx.x;
    if (e >= NEDGES) return;
    int s, d;
    if (g_is64) {
        const long long* p = (const long long*)ei;
        s = (int)p[e];
        d = (int)p[NEDGES + e];
    } else {
        const int* p = (const int*)ei;
        s = p[e];
        d = p[NEDGES + e];
    }
    g_src[e] = s;
    g_dst[e] = d;
    atomicAdd(&g_deg[d], 1);
}

// ---------------- exclusive scan of deg -> rowptr ----------------
__global__ __launch_bounds__(SCAN_B) void scanA_kernel() {
    __shared__ int s[SCAN_B];
    int tid = threadIdx.x;
    int i = blockIdx.x * SCAN_B + tid;
    int v = (i < NODES) ? g_deg[i] : 0;
    s[tid] = v;
    __syncthreads();
#pragma unroll
    for (int off = 1; off < SCAN_B; off <<= 1) {
        int t = (tid >= off) ? s[tid - off] : 0;
        __syncthreads();
        s[tid] += t;
        __syncthreads();
    }
    if (i < NODES) g_rexcl[i] = s[tid] - v;
    if (tid == SCAN_B - 1) g_bsum[blockIdx.x] = s[tid];
}

__global__ __launch_bounds__(128) void scanB_kernel() {
    __shared__ int s[128];
    int tid = threadIdx.x;
    int v = (tid < NSCANB) ? g_bsum[tid] : 0;
    s[tid] = v;
    __syncthreads();
#pragma unroll
    for (int off = 1; off < 128; off <<= 1) {
        int t = (tid >= off) ? s[tid - off] : 0;
        __syncthreads();
        s[tid] += t;
        __syncthreads();
    }
    if (tid < NSCANB) g_boff[tid] = s[tid] - v;   // exclusive
    if (tid == 0) g_rowptr[NODES] = NEDGES;
}

__global__ void scanC_kernel() {
    int i = blockIdx.x * blockDim.x + threadIdx.x;
    if (i >= NODES) return;
    g_rowptr[i] = g_rexcl[i] + g_boff[i >> 10];
}

__global__ void dinv_kernel() {
    int i = blockIdx.x * blockDim.x + threadIdx.x;
    if (i >= NODES) return;
    g_dinv[i] = rsqrtf((float)g_deg[i] + 1.0f);   // +1 = self loop
}

// counting-sort placement: group src by dst
__global__ void place_kernel() {
    int e = blockIdx.x * blockDim.x + threadIdx.x;
    if (e >= NEDGES) return;
    int d = g_dst[e];
    int pos = g_rowptr[d] + atomicAdd(&g_cnt[d], 1);
    g_csrc[pos] = g_src[e];
}

// h'_init = dinv * h0
__global__ void prescale_kernel() {
    int t = blockIdx.x * blockDim.x + threadIdx.x;
    if (t >= NODES * 4) return;
    float di = g_dinv[t >> 2];
    float4 h = ((const float4*)g_h0)[t];
    ((float4*)g_hA)[t] = make_float4(di * h.x, di * h.y, di * h.z, di * h.w);
}

// ---------------- fused MLP: bf16 MMA + cp.async double-buffered pipeline ----------------
// smem rows stride 20 u32 (80B): frag LDS conflict-free; 16B async chunks land
// 4-lanes-per-bank-group (crossbar minimum).
#define BM 128
#define BN 64
#define ROWU 20                         // u32 stride per smem row (16 pairs + pad)
#define XBUFU (BM * ROWU)               // 2560
#define WBUFU (BN * ROWU)               // 1280
#define BUFU  (XBUFU + WBUFU)           // 3840 u32 per buffer; x2 = 30720B

__device__ __forceinline__ void issue_tile(unsigned* Xb, unsigned* Wb,
                                           int bm, int bn, int kp0, int tid) {
    // X tile: 128 rows x 4 chunks = 512 chunks, 2 per thread
#pragma unroll
    for (int it = 0; it < 2; it++) {
        int l = tid + it * 256;
        int m = l & 127;
        int c = l >> 7;
        cp_async16(Xb + m * ROWU + c * 4,
                   g_xp + (size_t)(bm + m) * 256 + kp0 + c * 4);
    }
    // W tile: 64 rows x 4 chunks = 256 chunks, 1 per thread
    {
        int n = tid & 63;
        int c = tid >> 6;
        cp_async16(Wb + n * ROWU + c * 4,
                   g_w1p + (size_t)(bn + n) * 256 + kp0 + c * 4);
    }
}

__global__ __launch_bounds__(256) void mlp_tc_kernel(
    const float* __restrict__ b1, const float* __restrict__ W2,
    const float* __restrict__ b2)
{
    __shared__ __align__(16) float sm[9344];   // loop: 2*BUFU=7680 u32; epi: 9344 f
    unsigned* base = (unsigned*)sm;

    const int tid  = threadIdx.x;
    const int lane = tid & 31;
    const int wid  = tid >> 5;
    const int warp_m = wid >> 1;
    const int warp_n = wid & 1;
    const int bm = blockIdx.y * BM;      // m-block on slow axis
    const int bn = blockIdx.x * BN;      // n-block on fast axis (L2 reuse of X)
    const int gID = lane >> 2;
    const int tig = lane & 3;

    float acc[2][4][4];
#pragma unroll
    for (int mt = 0; mt < 2; mt++)
#pragma unroll
        for (int nt = 0; nt < 4; nt++)
#pragma unroll
            for (int v = 0; v < 4; v++) acc[mt][nt][v] = 0.f;

    // prologue: tile 0 -> buffer 0
    issue_tile(base, base + XBUFU, bm, bn, 0, tid);
    CP_COMMIT();
    CP_WAIT0();
    __syncthreads();

    int cur = 0;
    for (int kp0 = 0; kp0 < 256; kp0 += 16) {     // pair units; 16 pairs per tile
        const bool has_next = (kp0 + 16 < 256);
        if (has_next) {
            unsigned* nb = base + (cur ^ 1) * BUFU;
            issue_tile(nb, nb + XBUFU, bm, bn, kp0 + 16, tid);
            CP_COMMIT();
        }

        unsigned* Xp = base + cur * BUFU;          // [m][ROWU]
        unsigned* Wp = Xp + XBUFU;                 // [n][ROWU]

#pragma unroll
        for (int ks = 0; ks < 2; ks++) {           // 2 x k16 per tile
            const int kb = ks * 8;                 // pair offset within tile
            unsigned a[2][4], b[4][2];
#pragma unroll
            for (int mt = 0; mt < 2; mt++) {
                int m = warp_m * 32 + mt * 16 + gID;
                a[mt][0] = Xp[m * ROWU + kb + tig];
                a[mt][1] = Xp[(m + 8) * ROWU + kb + tig];
                a[mt][2] = Xp[m * ROWU + kb + tig + 4];
                a[mt][3] = Xp[(m + 8) * ROWU + kb + tig + 4];
            }
#pragma unroll
            for (int nt = 0; nt < 4; nt++) {
                int n = warp_n * 32 + nt * 8 + gID;
                b[nt][0] = Wp[n * ROWU + kb + tig];
                b[nt][1] = Wp[n * ROWU + kb + tig + 4];
            }
#pragma unroll
            for (int mt = 0; mt < 2; mt++)
#pragma unroll
                for (int nt = 0; nt < 4; nt++) {
                    float* c = acc[mt][nt];
                    asm volatile(
                        "mma.sync.aligned.m16n8k16.row.col.f32.bf16.bf16.f32 "
                        "{%0,%1,%2,%3}, {%4,%5,%6,%7}, {%8,%9}, {%0,%1,%2,%3};"
                        : "+f"(c[0]), "+f"(c[1]), "+f"(c[2]), "+f"(c[3])
                        : "r"(a[mt][0]), "r"(a[mt][1]), "r"(a[mt][2]), "r"(a[mt][3]),
                          "r"(b[nt][0]), "r"(b[nt][1]));
                }
        }

        if (has_next) {
            CP_WAIT0();
            __syncthreads();
            cur ^= 1;
        }
    }
    __syncthreads();                             // epilogue reuses smem

    // epilogue: bias + relu -> smem tile [128][65]
    float* tile = sm;
    float* W2s  = sm + BM * 65;

#pragma unroll
    for (int mt = 0; mt < 2; mt++) {
        int r0 = warp_m * 32 + mt * 16 + gID;
        int r1 = r0 + 8;
#pragma unroll
        for (int nt = 0; nt < 4; nt++) {
            int c0 = warp_n * 32 + nt * 8 + 2 * tig;
            int c1 = c0 + 1;
            float bc0 = b1[bn + c0];
            float bc1 = b1[bn + c1];
            float v00 = acc[mt][nt][0] + bc0;
            float v01 = acc[mt][nt][1] + bc1;
            float v10 = acc[mt][nt][2] + bc0;
            float v11 = acc[mt][nt][3] + bc1;
            tile[r0 * 65 + c0] = v00 > 0.f ? v00 : 0.f;
            tile[r0 * 65 + c1] = v01 > 0.f ? v01 : 0.f;
            tile[r1 * 65 + c0] = v10 > 0.f ? v10 : 0.f;
            tile[r1 * 65 + c1] = v11 > 0.f ? v11 : 0.f;
        }
    }
    {
        int rr = tid >> 2;
        int cc = (tid & 3) * 4;
        *(float4*)(W2s + rr * OUTC + cc) =
            *(const float4*)(W2 + (size_t)(bn + rr) * OUTC + cc);
    }
    __syncthreads();

    int m2 = tid >> 1;
    int ch = (tid & 1) * 8;
    float acc2[8];
#pragma unroll
    for (int c = 0; c < 8; c++) acc2[c] = (blockIdx.x == 0) ? b2[ch + c] : 0.f;
#pragma unroll 8
    for (int k = 0; k < BN; k++) {
        float v = tile[m2 * 65 + k];
        float4 w0 = *(float4*)(W2s + k * OUTC + ch);
        float4 w1 = *(float4*)(W2s + k * OUTC + ch + 4);
        acc2[0] += v * w0.x; acc2[1] += v * w0.y;
        acc2[2] += v * w0.z; acc2[3] += v * w0.w;
        acc2[4] += v * w1.x; acc2[5] += v * w1.y;
        acc2[6] += v * w1.z; acc2[7] += v * w1.w;
    }
    int gm2 = bm + m2;
    if (gm2 < NODES) {
        red_add_f4(g_h0 + (size_t)gm2 * OUTC + ch,
                   make_float4(acc2[0], acc2[1], acc2[2], acc2[3]));
        red_add_f4(g_h0 + (size_t)gm2 * OUTC + ch + 4,
                   make_float4(acc2[4], acc2[5], acc2[6], acc2[7]));
    }
}

// ---------------- propagation: warp-per-node CSR gather, unroll x4 (best) ----------------
__global__ __launch_bounds__(256) void gather_kernel(int sin, int sout, int final_,
                                                     float* __restrict__ out) {
    int w = (blockIdx.x * blockDim.x + threadIdx.x) >> 5;   // node id
    if (w >= NODES) return;
    const int lane = threadIdx.x & 31;
    const int el   = lane >> 2;    // 0..7  edge slot
    const int q    = lane & 3;     // 0..3  channel quad
    const float4* __restrict__ hin = sel_in(sin);
    const int* __restrict__ csrc = g_csrc;
    const int end = g_rowptr[w + 1];

    float4 a0 = make_float4(0.f, 0.f, 0.f, 0.f);
    float4 a1 = make_float4(0.f, 0.f, 0.f, 0.f);
    int e = g_rowptr[w] + el;
    for (; e + 24 < end; e += 32) {
        int s0 = __ldg(&csrc[e]);
        int s1 = __ldg(&csrc[e + 8]);
        int s2 = __ldg(&csrc[e + 16]);
        int s3 = __ldg(&csrc[e + 24]);
        float4 v0 = hin[s0 * 4 + q];
        float4 v1 = hin[s1 * 4 + q];
        float4 v2 = hin[s2 * 4 + q];
        float4 v3 = hin[s3 * 4 + q];
        a0.x += v0.x + v1.x; a0.y += v0.y + v1.y;
        a0.z += v0.z + v1.z; a0.w += v0.w + v1.w;
        a1.x += v2.x + v3.x; a1.y += v2.y + v3.y;
        a1.z += v2.z + v3.z; a1.w += v2.w + v3.w;
    }
    for (; e < end; e += 8) {
        int s = __ldg(&csrc[e]);
        float4 v = hin[s * 4 + q];
        a0.x += v.x; a0.y += v.y; a0.z += v.z; a0.w += v.w;
    }
    float4 acc = make_float4(a0.x + a1.x, a0.y + a1.y, a0.z + a1.z, a0.w + a1.w);
#pragma unroll
    for (int off = 4; off <= 16; off <<= 1) {
        acc.x += __shfl_xor_sync(0xFFFFFFFFu, acc.x, off);
        acc.y += __shfl_xor_sync(0xFFFFFFFFu, acc.y, off);
        acc.z += __shfl_xor_sync(0xFFFFFFFFu, acc.z, off);
        acc.w += __shfl_xor_sync(0xFFFFFFFFu, acc.w, off);
    }

    float di = g_dinv[w];
    float4 hs  = hin[w * 4 + q];                 // h'[i] (scaled self)
    float4 h0v = ((const float4*)g_h0)[w * 4 + q];
    float4 o;
    o.x = 0.9f * di * (acc.x + hs.x) + 0.1f * h0v.x;
    o.y = 0.9f * di * (acc.y + hs.y) + 0.1f * h0v.y;
    o.z = 0.9f * di * (acc.z + hs.z) + 0.1f * h0v.z;
    o.w = 0.9f * di * (acc.w + hs.w) + 0.1f * h0v.w;

    if (!final_) {
        if (el == 0)
            sel_out(sout)[w * 4 + q] =
                make_float4(di * o.x, di * o.y, di * o.z, di * o.w);
    } else {
        float m = fmaxf(fmaxf(o.x, o.y), fmaxf(o.z, o.w));
        m = fmaxf(m, __shfl_xor_sync(0xFFFFFFFFu, m, 1));
        m = fmaxf(m, __shfl_xor_sync(0xFFFFFFFFu, m, 2));
        float ssum = expf(o.x - m) + expf(o.y - m) + expf(o.z - m) + expf(o.w - m);
        ssum += __shfl_xor_sync(0xFFFFFFFFu, ssum, 1);
        ssum += __shfl_xor_sync(0xFFFFFFFFu, ssum, 2);
        float ls = logf(ssum) + m;
        if (el == 0)
            ((float4*)out)[w * 4 + q] =
                make_float4(o.x - ls, o.y - ls, o.z - ls, o.w - ls);
    }
}

// ---------------- launch ----------------
extern "C" void kernel_launch(void* const* d_in, const int* in_sizes, int n_in,
                              void* d_out, int out_size)
{
    const float* x  = (const float*)d_in[0];
    const void* ei  = d_in[1];
    const float* W1 = (const float*)d_in[2];
    const float* b1 = (const float*)d_in[3];
    const float* W2 = (const float*)d_in[4];
    const float* b2 = (const float*)d_in[5];
    float* out      = (float*)d_out;

    const int conv_items = NODESP * 128 + HIDC * 256;

    detect_kernel<<<1, 32>>>((const int*)ei);                           // 1
    zero_kernel<<<(NODES * OUTC + 255) / 256, 256>>>();                 // 2
    conv_kernel<<<(conv_items + 255) / 256, 256>>>(x, W1);              // 3
    mlp_tc_kernel<<<dim3(HIDC / BN, (NODES + BM - 1) / BM), 256>>>(     // 4 <- profiled
        b1, W2, b2);
    edge_kernel<<<(NEDGES + 255) / 256, 256>>>(ei);
    scanA_kernel<<<NSCANB, SCAN_B>>>();
    scanB_kernel<<<1, 128>>>();
    scanC_kernel<<<(NODES + 255) / 256, 256>>>();
    dinv_kernel<<<(NODES + 255) / 256, 256>>>();
    place_kernel<<<(NEDGES + 255) / 256, 256>>>();
    prescale_kernel<<<(NODES * 4 + 255) / 256, 256>>>();

    int cur = 1;
    for (int t = 0; t < KITER; t++) {
        int nxt = (cur == 1) ? 2 : 1;
        int fin = (t == KITER - 1) ? 1 : 0;
        gather_kernel<<<(NODES * 32 + 255) / 256, 256>>>(cur, nxt, fin, out);
        cur = nxt;
    }
}

// round 16
// speedup vs baseline: 1.6913x; 1.0698x over previous
#include <cuda_runtime.h>
#include <cuda_bf16.h>
#include <math.h>

#define NODES 100000
#define NODESP (NODES + 128)     // padded rows for OOB-safe cp.async
#define NEDGES 3200000
#define INC 512
#define HIDC 256
#define OUTC 16
#define KITER 10
#define SCAN_B 1024
#define NSCANB ((NODES + SCAN_B - 1) / SCAN_B)   // 98

// ---------------- scratch (static device globals; no allocation) ----------------
__device__ __align__(16) float g_h0[NODES * OUTC];   // unscaled MLP output
__device__ __align__(16) float g_hA[NODES * OUTC];   // scaled h' ping
__device__ __align__(16) float g_hB[NODES * OUTC];   // scaled h' pong
__device__ __align__(16) unsigned g_xp[(size_t)NODESP * 256]; // bf16-pair X [m][kpair]
__device__ __align__(16) unsigned g_w1p[HIDC * 256];          // bf16-pair W1^T [n][kpair]
__device__ float g_dinv[NODES];
__device__ int   g_deg[NODES];
__device__ int   g_cnt[NODES];
__device__ int   g_rexcl[NODES];
__device__ int   g_bsum[NSCANB];
__device__ int   g_boff[NSCANB];
__device__ int   g_rowptr[NODES + 1];
__device__ int   g_src[NEDGES];
__device__ int   g_dst[NEDGES];
__device__ int   g_csrc[NEDGES];       // CSR: src ids grouped by dst
__device__ int   g_is64;

__device__ __forceinline__ void red_add_f4(float* addr, float4 v) {
    asm volatile("red.global.add.v4.f32 [%0], {%1, %2, %3, %4};"
                 :: "l"(addr), "f"(v.x), "f"(v.y), "f"(v.z), "f"(v.w)
                 : "memory");
}

__device__ __forceinline__ unsigned bf2_of(float a, float b) {
    __nv_bfloat162 h = __floats2bfloat162_rn(a, b);   // low = a, high = b
    return *reinterpret_cast<unsigned*>(&h);
}

__device__ __forceinline__ void cp_async16(void* smem_ptr, const void* gptr) {
    unsigned saddr = (unsigned)__cvta_generic_to_shared(smem_ptr);
    asm volatile("cp.async.ca.shared.global [%0], [%1], 16;"
                 :: "r"(saddr), "l"(gptr) : "memory");
}
#define CP_COMMIT() asm volatile("cp.async.commit_group;" ::: "memory")
#define CP_WAIT0()  asm volatile("cp.async.wait_group 0;" ::: "memory")

// scaled buffers (1 = hA, 2 = hB)
__device__ __forceinline__ const float4* sel_in(int s) {
    return (const float4*)(s == 1 ? g_hA : g_hB);
}
__device__ __forceinline__ float4* sel_out(int s) {
    return (float4*)(s == 1 ? g_hA : g_hB);
}

// ---------------- dtype detection for edge_index (int32 vs int64) ----------------
__global__ void detect_kernel(const int* __restrict__ ei32) {
    if (threadIdx.x == 0 && blockIdx.x == 0) {
        int s = 0;
#pragma unroll
        for (int i = 0; i < 64; i++) s |= ei32[2 * i + 1];
        g_is64 = (s == 0) ? 1 : 0;
    }
}

// ---------------- init ----------------
__global__ void zero_kernel() {
    int i = blockIdx.x * blockDim.x + threadIdx.x;
    if (i < NODES * OUTC) g_h0[i] = 0.f;
    if (i < NODES) { g_deg[i] = 0; g_cnt[i] = 0; }
}

// ---------------- one-time bf16 conversion: X -> g_xp, W1^T -> g_w1p ----------------
__global__ void conv_kernel(const float* __restrict__ x, const float* __restrict__ W1) {
    int i = blockIdx.x * blockDim.x + threadIdx.x;
    const int NXT = NODESP * 128;                 // X work items (2 pairs each)
    if (i < NXT) {
        int row = i >> 7;
        int q   = i & 127;
        uint2 o = make_uint2(0u, 0u);
        if (row < NODES) {
            float4 v = *(const float4*)(x + (size_t)row * INC + q * 4);
            o.x = bf2_of(v.x, v.y);
            o.y = bf2_of(v.z, v.w);
        }
        *(uint2*)(g_xp + (size_t)row * 256 + q * 2) = o;
    } else {
        int j = i - NXT;
        if (j < HIDC * 256) {                     // W1 pairs
            int p = j >> 8;                       // kpair 0..255
            int n = j & 255;                      // coalesced reads along n
            g_w1p[n * 256 + p] =
                bf2_of(W1[(size_t)(2 * p) * HIDC + n],
                       W1[(size_t)(2 * p + 1) * HIDC + n]);
        }
    }
}

// ---------------- edge prep ----------------
__global__ void edge_kernel(const void* __restrict__ ei) {
    int e = blockIdx.x * blockDim.x + threadIdx.x;
    if (e >= NEDGES) return;
    int s, d;
    if (g_is64) {
        const long long* p = (const long long*)ei;
        s = (int)p[e];
        d = (int)p[NEDGES + e];
    } else {
        const int* p = (const int*)ei;
        s = p[e];
        d = p[NEDGES + e];
    }
    g_src[e] = s;
    g_dst[e] = d;
    atomicAdd(&g_deg[d], 1);
}

// ---------------- exclusive scan of deg -> rowptr ----------------
__global__ __launch_bounds__(SCAN_B) void scanA_kernel() {
    __shared__ int s[SCAN_B];
    int tid = threadIdx.x;
    int i = blockIdx.x * SCAN_B + tid;
    int v = (i < NODES) ? g_deg[i] : 0;
    s[tid] = v;
    __syncthreads();
#pragma unroll
    for (int off = 1; off < SCAN_B; off <<= 1) {
        int t = (tid >= off) ? s[tid - off] : 0;
        __syncthreads();
        s[tid] += t;
        __syncthreads();
    }
    if (i < NODES) g_rexcl[i] = s[tid] - v;
    if (tid == SCAN_B - 1) g_bsum[blockIdx.x] = s[tid];
}

__global__ __launch_bounds__(128) void scanB_kernel() {
    __shared__ int s[128];
    int tid = threadIdx.x;
    int v = (tid < NSCANB) ? g_bsum[tid] : 0;
    s[tid] = v;
    __syncthreads();
#pragma unroll
    for (int off = 1; off < 128; off <<= 1) {
        int t = (tid >= off) ? s[tid - off] : 0;
        __syncthreads();
        s[tid] += t;
        __syncthreads();
    }
    if (tid < NSCANB) g_boff[tid] = s[tid] - v;   // exclusive
    if (tid == 0) g_rowptr[NODES] = NEDGES;
}

__global__ void scanC_kernel() {
    int i = blockIdx.x * blockDim.x + threadIdx.x;
    if (i >= NODES) return;
    g_rowptr[i] = g_rexcl[i] + g_boff[i >> 10];
}

__global__ void dinv_kernel() {
    int i = blockIdx.x * blockDim.x + threadIdx.x;
    if (i >= NODES) return;
    g_dinv[i] = rsqrtf((float)g_deg[i] + 1.0f);   // +1 = self loop
}

// counting-sort placement: group src by dst
__global__ void place_kernel() {
    int e = blockIdx.x * blockDim.x + threadIdx.x;
    if (e >= NEDGES) return;
    int d = g_dst[e];
    int pos = g_rowptr[d] + atomicAdd(&g_cnt[d], 1);
    g_csrc[pos] = g_src[e];
}

// h'_init = dinv * h0
__global__ void prescale_kernel() {
    int t = blockIdx.x * blockDim.x + threadIdx.x;
    if (t >= NODES * 4) return;
    float di = g_dinv[t >> 2];
    float4 h = ((const float4*)g_h0)[t];
    ((float4*)g_hA)[t] = make_float4(di * h.x, di * h.y, di * h.z, di * h.w);
}

// ---------------- fused MLP: bf16 MMA, BN=128, cp.async pipeline ----------------
#define BM 128
#define BN 128
#define ROWU 20                         // u32 stride per smem row (16 pairs + pad)
#define XBUFU (BM * ROWU)               // 2560
#define WBUFU (BN * ROWU)               // 2560
#define BUFU  (XBUFU + WBUFU)           // 5120 u32 per buffer; x2 = 40960B

__device__ __forceinline__ void issue_tile(unsigned* Xb, unsigned* Wb,
                                           int bm, int bn, int kp0, int tid) {
    // X tile: 128 rows x 4 chunks = 512 chunks, 2 per thread
#pragma unroll
    for (int it = 0; it < 2; it++) {
        int l = tid + it * 256;
        int m = l & 127;
        int c = l >> 7;
        cp_async16(Xb + m * ROWU + c * 4,
                   g_xp + (size_t)(bm + m) * 256 + kp0 + c * 4);
    }
    // W tile: 128 rows x 4 chunks = 512 chunks, 2 per thread
#pragma unroll
    for (int it = 0; it < 2; it++) {
        int l = tid + it * 256;
        int n = l & 127;
        int c = l >> 7;
        cp_async16(Wb + n * ROWU + c * 4,
                   g_w1p + (size_t)(bn + n) * 256 + kp0 + c * 4);
    }
}

__global__ __launch_bounds__(256) void mlp_tc_kernel(
    const float* __restrict__ b1, const float* __restrict__ W2,
    const float* __restrict__ b2)
{
    __shared__ __align__(16) float sm[10368];  // loop: 2*BUFU=10240 u32; epi: 10368 f
    unsigned* base = (unsigned*)sm;

    const int tid  = threadIdx.x;
    const int lane = tid & 31;
    const int wid  = tid >> 5;
    const int warp_m = wid >> 1;         // 0..3 -> m 32-row band
    const int warp_n = wid & 1;          // 0..1 -> n 64-col band
    const int bm = blockIdx.y * BM;      // m-block on slow axis
    const int bn = blockIdx.x * BN;      // n-block on fast axis (L2 reuse of X)
    const int gID = lane >> 2;
    const int tig = lane & 3;

    float acc[2][8][4];
#pragma unroll
    for (int mt = 0; mt < 2; mt++)
#pragma unroll
        for (int nt = 0; nt < 8; nt++)
#pragma unroll
            for (int v = 0; v < 4; v++) acc[mt][nt][v] = 0.f;

    // prologue: tile 0 -> buffer 0
    issue_tile(base, base + XBUFU, bm, bn, 0, tid);
    CP_COMMIT();
    CP_WAIT0();
    __syncthreads();

    int cur = 0;
    for (int kp0 = 0; kp0 < 256; kp0 += 16) {     // pair units; 16 pairs per tile
        const bool has_next = (kp0 + 16 < 256);
        if (has_next) {
            unsigned* nb = base + (cur ^ 1) * BUFU;
            issue_tile(nb, nb + XBUFU, bm, bn, kp0 + 16, tid);
            CP_COMMIT();
        }

        unsigned* Xp = base + cur * BUFU;          // [m][ROWU]
        unsigned* Wp = Xp + XBUFU;                 // [n][ROWU]

#pragma unroll
        for (int ks = 0; ks < 2; ks++) {           // 2 x k16 per tile
            const int kb = ks * 8;                 // pair offset within tile
            unsigned a[2][4], b[8][2];
#pragma unroll
            for (int mt = 0; mt < 2; mt++) {
                int m = warp_m * 32 + mt * 16 + gID;
                a[mt][0] = Xp[m * ROWU + kb + tig];
                a[mt][1] = Xp[(m + 8) * ROWU + kb + tig];
                a[mt][2] = Xp[m * ROWU + kb + tig + 4];
                a[mt][3] = Xp[(m + 8) * ROWU + kb + tig + 4];
            }
#pragma unroll
            for (int nt = 0; nt < 8; nt++) {
                int n = warp_n * 64 + nt * 8 + gID;
                b[nt][0] = Wp[n * ROWU + kb + tig];
                b[nt][1] = Wp[n * ROWU + kb + tig + 4];
            }
#pragma unroll
            for (int mt = 0; mt < 2; mt++)
#pragma unroll
                for (int nt = 0; nt < 8; nt++) {
                    float* c = acc[mt][nt];
                    asm volatile(
                        "mma.sync.aligned.m16n8k16.row.col.f32.bf16.bf16.f32 "
                        "{%0,%1,%2,%3}, {%4,%5,%6,%7}, {%8,%9}, {%0,%1,%2,%3};"
                        : "+f"(c[0]), "+f"(c[1]), "+f"(c[2]), "+f"(c[3])
                        : "r"(a[mt][0]), "r"(a[mt][1]), "r"(a[mt][2]), "r"(a[mt][3]),
                          "r"(b[nt][0]), "r"(b[nt][1]));
                }
        }

        if (has_next) {
            CP_WAIT0();
            __syncthreads();
            cur ^= 1;
        }
    }
    __syncthreads();                             // epilogue reuses smem

    // epilogue in two 64-col passes: bias+relu -> tile[128][65]; layer2 partial
    float* tile = sm;                 // [BM][65] = 8320 floats
    float* W2s  = sm + BM * 65;       // [BN][OUTC] = 2048 floats

    // stage W2 slice [bn:bn+128, 0:16]
#pragma unroll
    for (int it = 0; it < 2; it++) {
        int l = tid + it * 256;
        int rr = l >> 2;
        int cc = (l & 3) * 4;
        *(float4*)(W2s + rr * OUTC + cc) =
            *(const float4*)(W2 + (size_t)(bn + rr) * OUTC + cc);
    }

    int m2 = tid >> 1;
    int ch = (tid & 1) * 8;
    float acc2[8];
#pragma unroll
    for (int c = 0; c < 8; c++) acc2[c] = (blockIdx.x == 0) ? b2[ch + c] : 0.f;

#pragma unroll
    for (int p = 0; p < 2; p++) {
        if (warp_n == p) {               // 4 warps stage their 64-col band
#pragma unroll
            for (int mt = 0; mt < 2; mt++) {
                int r0 = warp_m * 32 + mt * 16 + gID;
                int r1 = r0 + 8;
#pragma unroll
                for (int nt = 0; nt < 8; nt++) {
                    int cl = nt * 8 + 2 * tig;           // 0..63 local col
                    int cg = p * 64 + cl;                // block col
                    float bc0 = b1[bn + cg];
                    float bc1 = b1[bn + cg + 1];
                    float v00 = acc[mt][nt][0] + bc0;
                    float v01 = acc[mt][nt][1] + bc1;
                    float v10 = acc[mt][nt][2] + bc0;
                    float v11 = acc[mt][nt][3] + bc1;
                    tile[r0 * 65 + cl]     = v00 > 0.f ? v00 : 0.f;
                    tile[r0 * 65 + cl + 1] = v01 > 0.f ? v01 : 0.f;
                    tile[r1 * 65 + cl]     = v10 > 0.f ? v10 : 0.f;
                    tile[r1 * 65 + cl + 1] = v11 > 0.f ? v11 : 0.f;
                }
            }
        }
        __syncthreads();
#pragma unroll 8
        for (int k = 0; k < 64; k++) {
            float v = tile[m2 * 65 + k];
            float4 w0 = *(float4*)(W2s + (p * 64 + k) * OUTC + ch);
            float4 w1 = *(float4*)(W2s + (p * 64 + k) * OUTC + ch + 4);
            acc2[0] += v * w0.x; acc2[1] += v * w0.y;
            acc2[2] += v * w0.z; acc2[3] += v * w0.w;
            acc2[4] += v * w1.x; acc2[5] += v * w1.y;
            acc2[6] += v * w1.z; acc2[7] += v * w1.w;
        }
        __syncthreads();
    }

    int gm2 = bm + m2;
    if (gm2 < NODES) {
        red_add_f4(g_h0 + (size_t)gm2 * OUTC + ch,
                   make_float4(acc2[0], acc2[1], acc2[2], acc2[3]));
        red_add_f4(g_h0 + (size_t)gm2 * OUTC + ch + 4,
                   make_float4(acc2[4], acc2[5], acc2[6], acc2[7]));
    }
}

// ---------------- propagation: warp-per-node CSR gather, unroll x4 (best) ----------------
__global__ __launch_bounds__(256) void gather_kernel(int sin, int sout, int final_,
                                                     float* __restrict__ out) {
    int w = (blockIdx.x * blockDim.x + threadIdx.x) >> 5;   // node id
    if (w >= NODES) return;
    const int lane = threadIdx.x & 31;
    const int el   = lane >> 2;    // 0..7  edge slot
    const int q    = lane & 3;     // 0..3  channel quad
    const float4* __restrict__ hin = sel_in(sin);
    const int* __restrict__ csrc = g_csrc;
    const int end = g_rowptr[w + 1];

    float4 a0 = make_float4(0.f, 0.f, 0.f, 0.f);
    float4 a1 = make_float4(0.f, 0.f, 0.f, 0.f);
    int e = g_rowptr[w] + el;
    for (; e + 24 < end; e += 32) {
        int s0 = __ldg(&csrc[e]);
        int s1 = __ldg(&csrc[e + 8]);
        int s2 = __ldg(&csrc[e + 16]);
        int s3 = __ldg(&csrc[e + 24]);
        float4 v0 = hin[s0 * 4 + q];
        float4 v1 = hin[s1 * 4 + q];
        float4 v2 = hin[s2 * 4 + q];
        float4 v3 = hin[s3 * 4 + q];
        a0.x += v0.x + v1.x; a0.y += v0.y + v1.y;
        a0.z += v0.z + v1.z; a0.w += v0.w + v1.w;
        a1.x += v2.x + v3.x; a1.y += v2.y + v3.y;
        a1.z += v2.z + v3.z; a1.w += v2.w + v3.w;
    }
    for (; e < end; e += 8) {
        int s = __ldg(&csrc[e]);
        float4 v = hin[s * 4 + q];
        a0.x += v.x; a0.y += v.y; a0.z += v.z; a0.w += v.w;
    }
    float4 acc = make_float4(a0.x + a1.x, a0.y + a1.y, a0.z + a1.z, a0.w + a1.w);
#pragma unroll
    for (int off = 4; off <= 16; off <<= 1) {
        acc.x += __shfl_xor_sync(0xFFFFFFFFu, acc.x, off);
        acc.y += __shfl_xor_sync(0xFFFFFFFFu, acc.y, off);
        acc.z += __shfl_xor_sync(0xFFFFFFFFu, acc.z, off);
        acc.w += __shfl_xor_sync(0xFFFFFFFFu, acc.w, off);
    }

    float di = g_dinv[w];
    float4 hs  = hin[w * 4 + q];                 // h'[i] (scaled self)
    float4 h0v = ((const float4*)g_h0)[w * 4 + q];
    float4 o;
    o.x = 0.9f * di * (acc.x + hs.x) + 0.1f * h0v.x;
    o.y = 0.9f * di * (acc.y + hs.y) + 0.1f * h0v.y;
    o.z = 0.9f * di * (acc.z + hs.z) + 0.1f * h0v.z;
    o.w = 0.9f * di * (acc.w + hs.w) + 0.1f * h0v.w;

    if (!final_) {
        if (el == 0)
            sel_out(sout)[w * 4 + q] =
                make_float4(di * o.x, di * o.y, di * o.z, di * o.w);
    } else {
        float m = fmaxf(fmaxf(o.x, o.y), fmaxf(o.z, o.w));
        m = fmaxf(m, __shfl_xor_sync(0xFFFFFFFFu, m, 1));
        m = fmaxf(m, __shfl_xor_sync(0xFFFFFFFFu, m, 2));
        float ssum = expf(o.x - m) + expf(o.y - m) + expf(o.z - m) + expf(o.w - m);
        ssum += __shfl_xor_sync(0xFFFFFFFFu, ssum, 1);
        ssum += __shfl_xor_sync(0xFFFFFFFFu, ssum, 2);
        float ls = logf(ssum) + m;
        if (el == 0)
            ((float4*)out)[w * 4 + q] =
                make_float4(o.x - ls, o.y - ls, o.z - ls, o.w - ls);
    }
}

// ---------------- launch ----------------
extern "C" void kernel_launch(void* const* d_in, const int* in_sizes, int n_in,
                              void* d_out, int out_size)
{
    const float* x  = (const float*)d_in[0];
    const void* ei  = d_in[1];
    const float* W1 = (const float*)d_in[2];
    const float* b1 = (const float*)d_in[3];
    const float* W2 = (const float*)d_in[4];
    const float* b2 = (const float*)d_in[5];
    float* out      = (float*)d_out;

    const int conv_items = NODESP * 128 + HIDC * 256;

    detect_kernel<<<1, 32>>>((const int*)ei);                           // 1
    zero_kernel<<<(NODES * OUTC + 255) / 256, 256>>>();                 // 2
    conv_kernel<<<(conv_items + 255) / 256, 256>>>(x, W1);              // 3
    mlp_tc_kernel<<<dim3(HIDC / BN, (NODES + BM - 1) / BM), 256>>>(     // 4 <- profiled
        b1, W2, b2);
    edge_kernel<<<(NEDGES + 255) / 256, 256>>>(ei);
    scanA_kernel<<<NSCANB, SCAN_B>>>();
    scanB_kernel<<<1, 128>>>();
    scanC_kernel<<<(NODES + 255) / 256, 256>>>();
    dinv_kernel<<<(NODES + 255) / 256, 256>>>();
    place_kernel<<<(NEDGES + 255) / 256, 256>>>();
    prescale_kernel<<<(NODES * 4 + 255) / 256, 256>>>();

    int cur = 1;
    for (int t = 0; t < KITER; t++) {
        int nxt = (cur == 1) ? 2 : 1;
        int fin = (t == KITER - 1) ? 1 : 0;
        gather_kernel<<<(NODES * 32 + 255) / 256, 256>>>(cur, nxt, fin, out);
        cur = nxt;
    }
}